// round 1
// baseline (speedup 1.0000x reference)
#include <cuda_runtime.h>

// Problem constants
namespace {
constexpr int kB  = 4;
constexpr int kT  = 4096;
constexpr int kC  = 1024;
constexpr int kHD = 64;
constexpr int kM  = kB * kT;            // 16384 rows
constexpr float kScale  = 0.125f;       // 1/sqrt(64)
constexpr float kNegBig = -1e30f;
}

// Scratch for projections (allocation-free rule: __device__ globals)
__device__ float g_q[kM * kHD];
__device__ float g_k[kM * kHD];
__device__ float g_v[kM * kHD];

// ---------------------------------------------------------------------------
// Kernel 1: QKV projection. grid = (kM/64, 3), block = 256.
// Computes a 64x64 output tile of one of q/k/v with 4x4 register tiles.
// Shared tiles stored k-major (transposed X) so inner-loop loads are float4
// broadcasts across the 16-thread row/col groups.
// ---------------------------------------------------------------------------
__global__ __launch_bounds__(256) void proj_kernel(
    const float* __restrict__ x, const float* __restrict__ Wq,
    const float* __restrict__ Wk, const float* __restrict__ Wv) {
  __shared__ float Xs[16][68];   // [k][row]
  __shared__ float Ws[16][68];   // [k][col]
  const float* W = (blockIdx.y == 0) ? Wq : (blockIdx.y == 1) ? Wk : Wv;
  float* outp    = (blockIdx.y == 0) ? g_q : (blockIdx.y == 1) ? g_k : g_v;
  const int row0 = blockIdx.x * 64;
  const int tid  = threadIdx.x;
  const int tx = tid & 15, ty = tid >> 4;
  const int lrow = tid >> 2, lkq = tid & 3;   // X-tile loader mapping
  const int wkk  = tid >> 4, wc4 = tid & 15;  // W-tile loader mapping

  float acc[4][4] = {};
  for (int k0 = 0; k0 < kC; k0 += 16) {
    float4 xa = *(const float4*)&x[(size_t)(row0 + lrow) * kC + k0 + lkq * 4];
    Xs[lkq * 4 + 0][lrow] = xa.x;
    Xs[lkq * 4 + 1][lrow] = xa.y;
    Xs[lkq * 4 + 2][lrow] = xa.z;
    Xs[lkq * 4 + 3][lrow] = xa.w;
    *(float4*)&Ws[wkk][wc4 * 4] =
        *(const float4*)&W[(size_t)(k0 + wkk) * kHD + wc4 * 4];
    __syncthreads();
#pragma unroll
    for (int kk = 0; kk < 16; ++kk) {
      float4 a  = *(const float4*)&Xs[kk][ty * 4];
      float4 bv = *(const float4*)&Ws[kk][tx * 4];
      float av[4] = {a.x, a.y, a.z, a.w};
      float bb[4] = {bv.x, bv.y, bv.z, bv.w};
#pragma unroll
      for (int i = 0; i < 4; ++i)
#pragma unroll
        for (int j = 0; j < 4; ++j) acc[i][j] += av[i] * bb[j];
    }
    __syncthreads();
  }
#pragma unroll
  for (int i = 0; i < 4; ++i) {
    float4 ov = make_float4(acc[i][0], acc[i][1], acc[i][2], acc[i][3]);
    *(float4*)&outp[(size_t)(row0 + ty * 4 + i) * kHD + tx * 4] = ov;
  }
}

// ---------------------------------------------------------------------------
// Kernel 2: causal flash attention. grid = (kT/64, kB), block = 256.
// Each block: 64 query rows; loops over key tiles s0 = 0..t0.
// Register tiles: S/P 4x4, O 4x4 per thread (16x16 thread grid).
// Online softmax: per-row stats via width-16 shfl reductions.
// ---------------------------------------------------------------------------
__global__ __launch_bounds__(256) void attn_kernel(
    const int* __restrict__ pmask, float* __restrict__ out) {
  extern __shared__ float sm[];
  float* Qs   = sm;               // [64][68]  (d, i) transposed
  float* Ks   = Qs + 64 * 68;     // [64][68]  (d, j) transposed
  float* Vs   = Ks + 64 * 68;     // [64][68]  (j, d)
  float* Ps   = Vs + 64 * 68;     // [64][68]  (j, i) transposed
  float* madd = Ps + 64 * 68;     // [64] additive key mask

  const int b  = blockIdx.y;
  const int qi = (gridDim.x - 1) - blockIdx.x;   // heavy tiles first
  const int t0 = qi * 64;
  const int tid = threadIdx.x;
  const int tx = tid & 15, ty = tid >> 4;

  // Load Q tile transposed: Qs[d][i]
  const float* qbase = g_q + ((size_t)b * kT + t0) * kHD;
#pragma unroll
  for (int r = 0; r < 4; ++r) {
    int e = tid + r * 256;
    int i = e >> 4, dq = e & 15;
    float4 v = *(const float4*)&qbase[i * kHD + dq * 4];
    Qs[(dq * 4 + 0) * 68 + i] = v.x;
    Qs[(dq * 4 + 1) * 68 + i] = v.y;
    Qs[(dq * 4 + 2) * 68 + i] = v.z;
    Qs[(dq * 4 + 3) * 68 + i] = v.w;
  }

  float o[4][4]  = {};
  float mcur[4]  = {kNegBig, kNegBig, kNegBig, kNegBig};
  float lcur[4]  = {};

  for (int s0 = 0; s0 <= t0; s0 += 64) {
    __syncthreads();  // prior-iter PV readers done; Q ready on first iter
    const float* kbase = g_k + ((size_t)b * kT + s0) * kHD;
    const float* vbase = g_v + ((size_t)b * kT + s0) * kHD;
#pragma unroll
    for (int r = 0; r < 4; ++r) {
      int e = tid + r * 256;
      int j = e >> 4, dq = e & 15;
      float4 kv = *(const float4*)&kbase[j * kHD + dq * 4];
      Ks[(dq * 4 + 0) * 68 + j] = kv.x;
      Ks[(dq * 4 + 1) * 68 + j] = kv.y;
      Ks[(dq * 4 + 2) * 68 + j] = kv.z;
      Ks[(dq * 4 + 3) * 68 + j] = kv.w;
      *(float4*)&Vs[j * 68 + dq * 4] = *(const float4*)&vbase[j * kHD + dq * 4];
    }
    if (tid < 64)
      madd[tid] = (pmask[b * kT + s0 + tid] == 0) ? kNegBig : 0.0f;
    __syncthreads();

    // S = Q K^T (4x4 per thread)
    float s[4][4] = {};
#pragma unroll 8
    for (int d = 0; d < 64; ++d) {
      float4 a  = *(const float4*)&Qs[d * 68 + ty * 4];
      float4 bv = *(const float4*)&Ks[d * 68 + tx * 4];
      float av[4] = {a.x, a.y, a.z, a.w};
      float bb[4] = {bv.x, bv.y, bv.z, bv.w};
#pragma unroll
      for (int i = 0; i < 4; ++i)
#pragma unroll
        for (int j = 0; j < 4; ++j) s[i][j] += av[i] * bb[j];
    }
    {
      float ma[4] = {madd[tx * 4 + 0], madd[tx * 4 + 1],
                     madd[tx * 4 + 2], madd[tx * 4 + 3]};
#pragma unroll
      for (int i = 0; i < 4; ++i)
#pragma unroll
        for (int j = 0; j < 4; ++j) s[i][j] = s[i][j] * kScale + ma[j];
    }
    if (s0 == t0) {  // diagonal tile: causal mask (key > query)
#pragma unroll
      for (int i = 0; i < 4; ++i)
#pragma unroll
        for (int j = 0; j < 4; ++j)
          if (tx * 4 + j > ty * 4 + i) s[i][j] = kNegBig;
    }

    // Online softmax per row (rows ty*4..ty*4+3, distributed over 16 tx lanes)
#pragma unroll
    for (int i = 0; i < 4; ++i) {
      float rm = fmaxf(fmaxf(s[i][0], s[i][1]), fmaxf(s[i][2], s[i][3]));
#pragma unroll
      for (int off = 8; off; off >>= 1)
        rm = fmaxf(rm, __shfl_xor_sync(0xffffffffu, rm, off, 16));
      float mn = fmaxf(mcur[i], rm);
      float al = __expf(mcur[i] - mn);
      mcur[i] = mn;
      float rs = 0.0f;
      float pv[4];
#pragma unroll
      for (int j = 0; j < 4; ++j) {
        pv[j] = __expf(s[i][j] - mn);
        rs += pv[j];
      }
#pragma unroll
      for (int off = 8; off; off >>= 1)
        rs += __shfl_xor_sync(0xffffffffu, rs, off, 16);
      lcur[i] = lcur[i] * al + rs;
#pragma unroll
      for (int d = 0; d < 4; ++d) o[i][d] *= al;
#pragma unroll
      for (int j = 0; j < 4; ++j)
        Ps[(tx * 4 + j) * 68 + ty * 4 + i] = pv[j];
    }
    __syncthreads();

    // O += P V
#pragma unroll 8
    for (int j = 0; j < 64; ++j) {
      float4 pa = *(const float4*)&Ps[j * 68 + ty * 4];
      float4 vb = *(const float4*)&Vs[j * 68 + tx * 4];
      float pv[4] = {pa.x, pa.y, pa.z, pa.w};
      float vv[4] = {vb.x, vb.y, vb.z, vb.w};
#pragma unroll
      for (int i = 0; i < 4; ++i)
#pragma unroll
        for (int d = 0; d < 4; ++d) o[i][d] += pv[i] * vv[d];
    }
  }

  // Epilogue: normalize and store
#pragma unroll
  for (int i = 0; i < 4; ++i) {
    float inv = 1.0f / lcur[i];
    float4 ov = make_float4(o[i][0] * inv, o[i][1] * inv,
                            o[i][2] * inv, o[i][3] * inv);
    *(float4*)&out[((size_t)b * kT + t0 + ty * 4 + i) * kHD + tx * 4] = ov;
  }
}

// ---------------------------------------------------------------------------
extern "C" void kernel_launch(void* const* d_in, const int* in_sizes, int n_in,
                              void* d_out, int out_size) {
  const float* x  = (const float*)d_in[0];
  const float* Wq = (const float*)d_in[1];
  const float* Wk = (const float*)d_in[2];
  const float* Wv = (const float*)d_in[3];
  const int*   pm = (const int*)d_in[4];
  float* out = (float*)d_out;

  constexpr int kAttnSmem = (4 * 64 * 68 + 64) * (int)sizeof(float);  // 69888 B
  cudaFuncSetAttribute(attn_kernel, cudaFuncAttributeMaxDynamicSharedMemorySize,
                       kAttnSmem);

  proj_kernel<<<dim3(kM / 64, 3), 256>>>(x, Wq, Wk, Wv);
  attn_kernel<<<dim3(kT / 64, kB), 256, kAttnSmem>>>(pm, out);
}

// round 5
// speedup vs baseline: 2.2745x; 2.2745x over previous
#include <cuda_runtime.h>
#include <cuda_bf16.h>
#include <cstdint>

// Problem constants
namespace {
constexpr int kB  = 4;
constexpr int kT  = 4096;
constexpr int kC  = 1024;
constexpr int kHD = 64;
constexpr int kM  = kB * kT;            // 16384 rows
constexpr float kScale  = 0.125f;       // 1/sqrt(64)
constexpr float kNegBig = -1e30f;
}

// bf16 hi/lo split operands produced by the projection kernel (all row-major [t][d]).
__device__ __nv_bfloat16 g_qh[kM * kHD];
__device__ __nv_bfloat16 g_ql[kM * kHD];
__device__ __nv_bfloat16 g_kh[kM * kHD];
__device__ __nv_bfloat16 g_kl[kM * kHD];
__device__ __nv_bfloat16 g_vh[kM * kHD];
__device__ __nv_bfloat16 g_vl[kM * kHD];

// ---------------------------------------------------------------------------
// Helpers: sm_80-class tensor ops (legal on plain sm_100 target)
// ---------------------------------------------------------------------------
__device__ __forceinline__ uint32_t smem_u32(const void* p) {
  uint32_t a;
  asm("{ .reg .u64 t; cvta.to.shared.u64 t, %1; cvt.u32.u64 %0, t; }"
      : "=r"(a) : "l"(p));
  return a;
}
__device__ __forceinline__ uint32_t sw128(uint32_t off) {
  return off ^ ((off >> 3) & 0x70);
}
__device__ __forceinline__ void mma_bf16(float c[4], const uint32_t a[4],
                                         uint32_t b0, uint32_t b1) {
  asm volatile(
      "mma.sync.aligned.m16n8k16.row.col.f32.bf16.bf16.f32 "
      "{%0,%1,%2,%3}, {%4,%5,%6,%7}, {%8,%9}, {%0,%1,%2,%3};"
      : "+f"(c[0]), "+f"(c[1]), "+f"(c[2]), "+f"(c[3])
      : "r"(a[0]), "r"(a[1]), "r"(a[2]), "r"(a[3]), "r"(b0), "r"(b1));
}
__device__ __forceinline__ void ldsm_x4(uint32_t r[4], uint32_t addr) {
  asm volatile("ldmatrix.sync.aligned.m8n8.x4.shared.b16 {%0,%1,%2,%3}, [%4];"
               : "=r"(r[0]), "=r"(r[1]), "=r"(r[2]), "=r"(r[3]) : "r"(addr));
}
__device__ __forceinline__ void ldsm_x2(uint32_t& r0, uint32_t& r1,
                                        uint32_t addr) {
  asm volatile("ldmatrix.sync.aligned.m8n8.x2.shared.b16 {%0,%1}, [%2];"
               : "=r"(r0), "=r"(r1) : "r"(addr));
}
__device__ __forceinline__ void ldsm_x2t(uint32_t& r0, uint32_t& r1,
                                         uint32_t addr) {
  asm volatile("ldmatrix.sync.aligned.m8n8.x2.trans.shared.b16 {%0,%1}, [%2];"
               : "=r"(r0), "=r"(r1) : "r"(addr));
}
// Pack two fp32 into bf16x2 (lower half = a0) plus the residual bf16x2.
__device__ __forceinline__ void split_pack(float a0, float a1, uint32_t& h,
                                           uint32_t& l) {
  asm("cvt.rn.bf16x2.f32 %0, %1, %2;" : "=r"(h) : "f"(a1), "f"(a0));
  float f0 = __uint_as_float(h << 16);
  float f1 = __uint_as_float(h & 0xFFFF0000u);
  asm("cvt.rn.bf16x2.f32 %0, %1, %2;" : "=r"(l) : "f"(a1 - f1), "f"(a0 - f0));
}

// ---------------------------------------------------------------------------
// Kernel 1: QKV projection on tensor cores, bf16 split-3 fp32 emulation.
// grid = kM/128, block = 256 (8 warps; warp w owns rows w*16..w*16+15).
// Per 64-wide k-chunk: x rows + all three W chunks are split hi/lo into smem;
// x fragments are reused across the three heads.
// ---------------------------------------------------------------------------
namespace {
constexpr int pXH = 0, pXL = 16384;       // 128 rows x 128B
constexpr int pW  = 32768;                // per head: hi at h*16384, lo +8192
constexpr int kProjSmem = 32768 + 3 * 16384;  // 81920
}

__global__ __launch_bounds__(256) void proj_kernel(
    const float* __restrict__ x, const float* __restrict__ Wq,
    const float* __restrict__ Wk, const float* __restrict__ Wv) {
  extern __shared__ char smem[];
  const uint32_t sb = smem_u32(smem);
  const int tid = threadIdx.x;
  const int w = tid >> 5, lane = tid & 31;
  const int g = lane >> 2, tg = lane & 3;
  const int row0 = blockIdx.x * 128;

  float acc[3][8][4] = {};

  for (int kc = 0; kc < 16; ++kc) {
    __syncthreads();  // previous iteration's fragment loads done
    // ---- split x chunk [128 x 64] into hi/lo smem ----
#pragma unroll
    for (int rep = 0; rep < 16; ++rep) {
      const int e = tid + rep * 256;
      const int row = e >> 5, pr = e & 31;  // 32 float2 per row
      float2 xv = *(const float2*)&x[(size_t)(row0 + row) * kC + kc * 64 + pr * 2];
      uint32_t h, l;
      split_pack(xv.x, xv.y, h, l);
      const uint32_t sw = sw128((uint32_t)(row * 128 + pr * 4));
      *(uint32_t*)(smem + pXH + sw) = h;
      *(uint32_t*)(smem + pXL + sw) = l;
    }
    // ---- split W chunks [64 x 64] x 3 heads into hi/lo smem ----
#pragma unroll
    for (int rep = 0; rep < 24; ++rep) {
      const int e = tid + rep * 256;
      const int h3 = e >> 11;               // 2048 float2 per head
      const int rem = e & 2047;
      const int row = rem >> 5, pr = rem & 31;
      const float* Wp = (h3 == 0) ? Wq : (h3 == 1) ? Wk : Wv;
      float2 wv = *(const float2*)&Wp[(size_t)(kc * 64 + row) * kHD + pr * 2];
      uint32_t h, l;
      split_pack(wv.x, wv.y, h, l);
      const uint32_t sw = sw128((uint32_t)(row * 128 + pr * 4));
      *(uint32_t*)(smem + pW + h3 * 16384 + sw) = h;
      *(uint32_t*)(smem + pW + h3 * 16384 + 8192 + sw) = l;
    }
    __syncthreads();

    // ---- A fragments of x (hi/lo), 4 k-steps ----
    uint32_t xh[4][4], xl[4][4];
    const int arow = w * 16 + (lane & 15);
    const int acb = lane >> 4;
#pragma unroll
    for (int ks = 0; ks < 4; ++ks) {
      const uint32_t off = sw128((uint32_t)(arow * 128 + ks * 32 + acb * 16));
      ldsm_x4(xh[ks], sb + pXH + off);
      ldsm_x4(xl[ks], sb + pXL + off);
    }

    // ---- B = W (k-major rows): trans ldmatrix; 3-pass mma ----
    const int l15 = lane & 15;
    const int brow = (l15 & 7) + ((l15 >> 3) << 3);  // 0..15 within k16
#pragma unroll
    for (int h3 = 0; h3 < 3; ++h3) {
#pragma unroll
      for (int nb = 0; nb < 8; ++nb) {
#pragma unroll
        for (int ks = 0; ks < 4; ++ks) {
          const uint32_t off =
              sw128((uint32_t)((ks * 16 + brow) * 128 + nb * 16));
          uint32_t bh0, bh1, bl0, bl1;
          ldsm_x2t(bh0, bh1, sb + pW + h3 * 16384 + off);
          ldsm_x2t(bl0, bl1, sb + pW + h3 * 16384 + 8192 + off);
          mma_bf16(acc[h3][nb], xh[ks], bh0, bh1);
          mma_bf16(acc[h3][nb], xl[ks], bh0, bh1);
          mma_bf16(acc[h3][nb], xh[ks], bl0, bl1);
        }
      }
    }
  }

  // ---- epilogue: split fp32 accumulators to bf16 hi/lo in gmem ----
  const int r1 = row0 + w * 16 + g;
  const int r2 = r1 + 8;
#pragma unroll
  for (int h3 = 0; h3 < 3; ++h3) {
    __nv_bfloat16* hp = (h3 == 0) ? g_qh : (h3 == 1) ? g_kh : g_vh;
    __nv_bfloat16* lp = (h3 == 0) ? g_ql : (h3 == 1) ? g_kl : g_vl;
#pragma unroll
    for (int nb = 0; nb < 8; ++nb) {
      const int col = nb * 8 + tg * 2;
      uint32_t h, l;
      split_pack(acc[h3][nb][0], acc[h3][nb][1], h, l);
      *(uint32_t*)(hp + (size_t)r1 * kHD + col) = h;
      *(uint32_t*)(lp + (size_t)r1 * kHD + col) = l;
      split_pack(acc[h3][nb][2], acc[h3][nb][3], h, l);
      *(uint32_t*)(hp + (size_t)r2 * kHD + col) = h;
      *(uint32_t*)(lp + (size_t)r2 * kHD + col) = l;
    }
  }
}

// ---------------------------------------------------------------------------
// Kernel 2: FA2-style causal flash attention on mma.sync.
// grid = (64, 4), block = 128 (4 warps; warp w owns query rows w*16..+15).
// Key tiles of 64; K via non-trans ldmatrix (B = K^T exactly), V via trans.
// S C-fragments convert in-register to P A-fragments (hi/lo split).
// ---------------------------------------------------------------------------
namespace {
constexpr int aKH = 0, aKL = 8192, aVH = 16384, aVL = 24576;
constexpr int aQH = 32768, aQL = 40960;
constexpr int aMADD = 49152;
constexpr int kAttnSmem = 49152 + 256;
}

__global__ __launch_bounds__(128) void attn_kernel(
    const int* __restrict__ pmask, float* __restrict__ out) {
  extern __shared__ char smem[];
  const uint32_t sb = smem_u32(smem);
  const int tid = threadIdx.x;
  const int w = tid >> 5, lane = tid & 31;
  const int g = lane >> 2, tg = lane & 3;
  const int b = blockIdx.y;
  const int qi = (gridDim.x - 1) - blockIdx.x;  // heavy tiles first
  const int t0 = qi * 64;
  const int qg1 = t0 + w * 16 + g;      // this thread's two query rows
  const int qg2 = qg1 + 8;

  // ---- stage Q tile (64 x 64, hi/lo) into swizzled smem ----
#pragma unroll
  for (int rep = 0; rep < 4; ++rep) {
    const int e = tid + rep * 128;
    const int j = e >> 3, ch = e & 7;
    const uint32_t sw = sw128((uint32_t)(j * 128 + ch * 16));
    const size_t goff = (size_t)(b * kT + t0 + j) * kHD + ch * 8;
    *(uint4*)(smem + aQH + sw) = *(const uint4*)(g_qh + goff);
    *(uint4*)(smem + aQL + sw) = *(const uint4*)(g_ql + goff);
  }
  __syncthreads();

  // ---- resident Q fragments (hi/lo), 4 k-steps ----
  uint32_t qh[4][4], ql[4][4];
  {
    const int arow = w * 16 + (lane & 15);
    const int acb = lane >> 4;
#pragma unroll
    for (int ks = 0; ks < 4; ++ks) {
      const uint32_t off = sw128((uint32_t)(arow * 128 + ks * 32 + acb * 16));
      ldsm_x4(qh[ks], sb + aQH + off);
      ldsm_x4(ql[ks], sb + aQL + off);
    }
  }

  float O[8][4] = {};
  float m1 = kNegBig, m2 = kNegBig, l1 = 0.0f, l2 = 0.0f;
  const int ntiles = qi + 1;
  const int l15 = lane & 15;
  const int jrow = l15 & 7;               // ldmatrix row-address helpers
  const int khi = (l15 >> 3) ? 16 : 0;    // K: second k8 tile byte offset
  const int vrow8 = (l15 >> 3) ? 8 : 0;   // V: second k8 tile row offset

  for (int it = 0; it < ntiles; ++it) {
    const int s0 = it * 64;
    __syncthreads();  // all warps done with previous tile's smem
    // ---- stage K / V tiles (hi/lo) ----
#pragma unroll
    for (int rep = 0; rep < 4; ++rep) {
      const int e = tid + rep * 128;
      const int j = e >> 3, ch = e & 7;
      const uint32_t sw = sw128((uint32_t)(j * 128 + ch * 16));
      const size_t goff = (size_t)(b * kT + s0 + j) * kHD + ch * 8;
      *(uint4*)(smem + aKH + sw) = *(const uint4*)(g_kh + goff);
      *(uint4*)(smem + aKL + sw) = *(const uint4*)(g_kl + goff);
      *(uint4*)(smem + aVH + sw) = *(const uint4*)(g_vh + goff);
      *(uint4*)(smem + aVL + sw) = *(const uint4*)(g_vl + goff);
    }
    if (tid < 64)
      ((float*)(smem + aMADD))[tid] =
          (pmask[b * kT + s0 + tid] == 0) ? kNegBig : 0.0f;
    __syncthreads();

    // ---- S = Q K^T (3-pass split) ----
    float sc[8][4];
#pragma unroll
    for (int jb = 0; jb < 8; ++jb) {
      sc[jb][0] = sc[jb][1] = sc[jb][2] = sc[jb][3] = 0.0f;
#pragma unroll
      for (int ks = 0; ks < 4; ++ks) {
        const uint32_t off =
            sw128((uint32_t)((jb * 8 + jrow) * 128 + ks * 32 + khi));
        uint32_t kh0, kh1, kl0, kl1;
        ldsm_x2(kh0, kh1, sb + aKH + off);
        ldsm_x2(kl0, kl1, sb + aKL + off);
        mma_bf16(sc[jb], qh[ks], kh0, kh1);
        mma_bf16(sc[jb], ql[ks], kh0, kh1);
        mma_bf16(sc[jb], qh[ks], kl0, kl1);
      }
    }

    // ---- masked online softmax on fragment rows ----
    const float* madd = (const float*)(smem + aMADD);
    const bool diag = (it == ntiles - 1);
    float mx1 = kNegBig, mx2 = kNegBig;
#pragma unroll
    for (int jb = 0; jb < 8; ++jb) {
#pragma unroll
      for (int i = 0; i < 2; ++i) {
        const int jl = jb * 8 + tg * 2 + i;
        const float ma = madd[jl];
        float v1 = sc[jb][i] * kScale + ma;
        float v2 = sc[jb][2 + i] * kScale + ma;
        if (diag) {
          const int jglob = s0 + jl;
          if (jglob > qg1) v1 = kNegBig;
          if (jglob > qg2) v2 = kNegBig;
        }
        sc[jb][i] = v1;
        sc[jb][2 + i] = v2;
        mx1 = fmaxf(mx1, v1);
        mx2 = fmaxf(mx2, v2);
      }
    }
    mx1 = fmaxf(mx1, __shfl_xor_sync(0xffffffffu, mx1, 1));
    mx1 = fmaxf(mx1, __shfl_xor_sync(0xffffffffu, mx1, 2));
    mx2 = fmaxf(mx2, __shfl_xor_sync(0xffffffffu, mx2, 1));
    mx2 = fmaxf(mx2, __shfl_xor_sync(0xffffffffu, mx2, 2));
    const float mn1 = fmaxf(m1, mx1), mn2 = fmaxf(m2, mx2);
    const float al1 = __expf(m1 - mn1), al2 = __expf(m2 - mn2);
    m1 = mn1; m2 = mn2;
    float s1 = 0.0f, s2 = 0.0f;
#pragma unroll
    for (int jb = 0; jb < 8; ++jb) {
      sc[jb][0] = __expf(sc[jb][0] - mn1);
      sc[jb][1] = __expf(sc[jb][1] - mn1);
      sc[jb][2] = __expf(sc[jb][2] - mn2);
      sc[jb][3] = __expf(sc[jb][3] - mn2);
      s1 += sc[jb][0] + sc[jb][1];
      s2 += sc[jb][2] + sc[jb][3];
    }
    s1 += __shfl_xor_sync(0xffffffffu, s1, 1);
    s1 += __shfl_xor_sync(0xffffffffu, s1, 2);
    s2 += __shfl_xor_sync(0xffffffffu, s2, 1);
    s2 += __shfl_xor_sync(0xffffffffu, s2, 2);
    l1 = l1 * al1 + s1;
    l2 = l2 * al2 + s2;
#pragma unroll
    for (int nb = 0; nb < 8; ++nb) {
      O[nb][0] *= al1; O[nb][1] *= al1;
      O[nb][2] *= al2; O[nb][3] *= al2;
    }

    // ---- P C-frag -> A-frag (hi/lo), in registers ----
    uint32_t ph[4][4], pl[4][4];
#pragma unroll
    for (int ks = 0; ks < 4; ++ks) {
      const int jb0 = 2 * ks, jb1 = 2 * ks + 1;
      split_pack(sc[jb0][0], sc[jb0][1], ph[ks][0], pl[ks][0]);
      split_pack(sc[jb0][2], sc[jb0][3], ph[ks][1], pl[ks][1]);
      split_pack(sc[jb1][0], sc[jb1][1], ph[ks][2], pl[ks][2]);
      split_pack(sc[jb1][2], sc[jb1][3], ph[ks][3], pl[ks][3]);
    }

    // ---- O += P V (3-pass split), V via trans ldmatrix ----
#pragma unroll
    for (int nb = 0; nb < 8; ++nb) {
#pragma unroll
      for (int ks = 0; ks < 4; ++ks) {
        const uint32_t off =
            sw128((uint32_t)((ks * 16 + jrow + vrow8) * 128 + nb * 16));
        uint32_t vh0, vh1, vl0, vl1;
        ldsm_x2t(vh0, vh1, sb + aVH + off);
        ldsm_x2t(vl0, vl1, sb + aVL + off);
        mma_bf16(O[nb], ph[ks], vh0, vh1);
        mma_bf16(O[nb], pl[ks], vh0, vh1);
        mma_bf16(O[nb], ph[ks], vl0, vl1);
      }
    }
  }

  // ---- epilogue ----
  const float inv1 = 1.0f / l1, inv2 = 1.0f / l2;
  const size_t r1 = (size_t)(b * kT + qg1) * kHD;
  const size_t r2 = (size_t)(b * kT + qg2) * kHD;
#pragma unroll
  for (int nb = 0; nb < 8; ++nb) {
    const int col = nb * 8 + tg * 2;
    *(float2*)(out + r1 + col) = make_float2(O[nb][0] * inv1, O[nb][1] * inv1);
    *(float2*)(out + r2 + col) = make_float2(O[nb][2] * inv2, O[nb][3] * inv2);
  }
}

// ---------------------------------------------------------------------------
extern "C" void kernel_launch(void* const* d_in, const int* in_sizes, int n_in,
                              void* d_out, int out_size) {
  const float* x  = (const float*)d_in[0];
  const float* Wq = (const float*)d_in[1];
  const float* Wk = (const float*)d_in[2];
  const float* Wv = (const float*)d_in[3];
  const int*   pm = (const int*)d_in[4];
  float* out = (float*)d_out;

  cudaFuncSetAttribute(proj_kernel, cudaFuncAttributeMaxDynamicSharedMemorySize,
                       kProjSmem);
  cudaFuncSetAttribute(attn_kernel, cudaFuncAttributeMaxDynamicSharedMemorySize,
                       kAttnSmem);

  proj_kernel<<<kM / 128, 256, kProjSmem>>>(x, Wq, Wk, Wv);
  attn_kernel<<<dim3(64, kB), 128, kAttnSmem>>>(pm, out);
}

// round 6
// speedup vs baseline: 3.5682x; 1.5688x over previous
#include <cuda_runtime.h>
#include <cuda_bf16.h>
#include <cstdint>

// Problem constants
namespace {
constexpr int kB  = 4;
constexpr int kT  = 4096;
constexpr int kC  = 1024;
constexpr int kHD = 64;
constexpr int kM  = kB * kT;            // 16384 rows
constexpr float kScale  = 0.125f;       // 1/sqrt(64)
constexpr float kNegBig = -1e30f;
}

// bf16 hi/lo split operands (all row-major [t][64])
__device__ __nv_bfloat16 g_qh[kM * kHD];
__device__ __nv_bfloat16 g_ql[kM * kHD];
__device__ __nv_bfloat16 g_kh[kM * kHD];
__device__ __nv_bfloat16 g_kl[kM * kHD];
__device__ __nv_bfloat16 g_vh[kM * kHD];
__device__ __nv_bfloat16 g_vl[kM * kHD];
// Pre-split weights [3][1024][64]
__device__ __nv_bfloat16 g_wh[3 * kC * kHD];
__device__ __nv_bfloat16 g_wl[3 * kC * kHD];

// ---------------------------------------------------------------------------
// Helpers
// ---------------------------------------------------------------------------
__device__ __forceinline__ uint32_t smem_u32(const void* p) {
  uint32_t a;
  asm("{ .reg .u64 t; cvta.to.shared.u64 t, %1; cvt.u32.u64 %0, t; }"
      : "=r"(a) : "l"(p));
  return a;
}
__device__ __forceinline__ uint32_t sw128(uint32_t off) {
  return off ^ ((off >> 3) & 0x70);
}
__device__ __forceinline__ void mma_bf16(float c[4], const uint32_t a[4],
                                         uint32_t b0, uint32_t b1) {
  asm volatile(
      "mma.sync.aligned.m16n8k16.row.col.f32.bf16.bf16.f32 "
      "{%0,%1,%2,%3}, {%4,%5,%6,%7}, {%8,%9}, {%0,%1,%2,%3};"
      : "+f"(c[0]), "+f"(c[1]), "+f"(c[2]), "+f"(c[3])
      : "r"(a[0]), "r"(a[1]), "r"(a[2]), "r"(a[3]), "r"(b0), "r"(b1));
}
__device__ __forceinline__ void ldsm_x4(uint32_t r[4], uint32_t addr) {
  asm volatile("ldmatrix.sync.aligned.m8n8.x4.shared.b16 {%0,%1,%2,%3}, [%4];"
               : "=r"(r[0]), "=r"(r[1]), "=r"(r[2]), "=r"(r[3]) : "r"(addr));
}
__device__ __forceinline__ void ldsm_x4t(uint32_t r[4], uint32_t addr) {
  asm volatile("ldmatrix.sync.aligned.m8n8.x4.trans.shared.b16 {%0,%1,%2,%3}, [%4];"
               : "=r"(r[0]), "=r"(r[1]), "=r"(r[2]), "=r"(r[3]) : "r"(addr));
}
__device__ __forceinline__ void cp16(uint32_t dst, const void* src) {
  asm volatile("cp.async.cg.shared.global [%0], [%1], 16;" :: "r"(dst),
               "l"(__cvta_generic_to_global(src)));
}
#define CP_COMMIT() asm volatile("cp.async.commit_group;" ::: "memory")
#define CP_WAIT(n)  asm volatile("cp.async.wait_group %0;" :: "n"(n) : "memory")

// Pack two fp32 into bf16x2 (lower half = a0) plus the residual bf16x2.
__device__ __forceinline__ void split_pack(float a0, float a1, uint32_t& h,
                                           uint32_t& l) {
  asm("cvt.rn.bf16x2.f32 %0, %1, %2;" : "=r"(h) : "f"(a1), "f"(a0));
  float f0 = __uint_as_float(h << 16);
  float f1 = __uint_as_float(h & 0xFFFF0000u);
  asm("cvt.rn.bf16x2.f32 %0, %1, %2;" : "=r"(l) : "f"(a1 - f1), "f"(a0 - f0));
}

// ---------------------------------------------------------------------------
// Kernel 0: W pre-split (fp32 -> bf16 hi/lo). grid=192, block=256.
// ---------------------------------------------------------------------------
__global__ __launch_bounds__(256) void wsplit_kernel(
    const float* __restrict__ Wq, const float* __restrict__ Wk,
    const float* __restrict__ Wv) {
  int p = blockIdx.x * 256 + threadIdx.x;
#pragma unroll
  for (int rep = 0; rep < 2; ++rep, p += 49152) {
    const int h3 = p >> 15;          // 32768 float2 per head
    const int rem = p & 32767;
    const float* W = (h3 == 0) ? Wq : (h3 == 1) ? Wk : Wv;
    float2 wv = *(const float2*)&W[rem * 2];
    uint32_t h, l;
    split_pack(wv.x, wv.y, h, l);
    *(uint32_t*)(g_wh + (size_t)h3 * kC * kHD + rem * 2) = h;
    *(uint32_t*)(g_wl + (size_t)h3 * kC * kHD + rem * 2) = l;
  }
}

// ---------------------------------------------------------------------------
// Kernel 1: QKV projection. grid = kM/64, block = 128 (4 warps x 16 rows).
// x A-fragments gathered directly from gmem (split in regs); W hi/lo staged
// through cp.async double-buffered smem; B via x4 trans ldmatrix.
// ---------------------------------------------------------------------------
namespace {
constexpr int kProjStage = 49152;            // 6 tiles x 8KB (3 heads x hi/lo)
constexpr int kProjSmem  = 2 * kProjStage;   // 98304
}

__global__ __launch_bounds__(128) void proj_kernel(const float* __restrict__ x) {
  extern __shared__ char smem[];
  const uint32_t sb = smem_u32(smem);
  const int tid = threadIdx.x;
  const int w = tid >> 5, lane = tid & 31;
  const int g = lane >> 2, tg = lane & 3;
  const int row0 = blockIdx.x * 64;
  // trans-ldsm x4 per-lane address parts: matrices = (k-half, n-tile)
  const int brow = (lane & 7) + ((lane >> 3) & 1) * 8;
  const int bnb = lane >> 4;

  auto issue_w = [&](int kc, int stage) {
    const uint32_t sbase = sb + stage * kProjStage;
#pragma unroll
    for (int rep = 0; rep < 24; ++rep) {
      const int e = tid + rep * 128;
      const int ch = e & 7, row = (e >> 3) & 63, rest = e >> 9;
      const int h3 = rest >> 1, hl = rest & 1;
      const __nv_bfloat16* src = (hl ? g_wl : g_wh) +
          ((size_t)h3 * kC + kc * 64 + row) * kHD + ch * 8;
      cp16(sbase + h3 * 16384 + hl * 8192 + sw128(row * 128 + ch * 16), src);
    }
    CP_COMMIT();
  };

  float acc[24][4] = {};
  issue_w(0, 0);

  const int r1 = row0 + w * 16 + g;
  for (int kc = 0; kc < 16; ++kc) {
    // ---- x A-fragments straight from gmem, split in registers ----
    uint32_t xh[4][4], xl[4][4];
#pragma unroll
    for (int ks = 0; ks < 4; ++ks) {
      const float* p1 = x + (size_t)r1 * kC + kc * 64 + ks * 16 + tg * 2;
      const float* p2 = p1 + (size_t)8 * kC;
      float2 v00 = *(const float2*)p1;
      float2 v10 = *(const float2*)p2;
      float2 v01 = *(const float2*)(p1 + 8);
      float2 v11 = *(const float2*)(p2 + 8);
      split_pack(v00.x, v00.y, xh[ks][0], xl[ks][0]);
      split_pack(v10.x, v10.y, xh[ks][1], xl[ks][1]);
      split_pack(v01.x, v01.y, xh[ks][2], xl[ks][2]);
      split_pack(v11.x, v11.y, xh[ks][3], xl[ks][3]);
    }
    if (kc < 15) { issue_w(kc + 1, (kc + 1) & 1); CP_WAIT(1); }
    else CP_WAIT(0);
    __syncthreads();

    const uint32_t sbase = sb + (kc & 1) * kProjStage;
#pragma unroll
    for (int h3 = 0; h3 < 3; ++h3) {
#pragma unroll
      for (int nb2 = 0; nb2 < 4; ++nb2) {
        float* a0 = acc[h3 * 8 + 2 * nb2];
        float* a1 = acc[h3 * 8 + 2 * nb2 + 1];
#pragma unroll
        for (int ks = 0; ks < 4; ++ks) {
          const uint32_t off =
              sw128((uint32_t)((ks * 16 + brow) * 128 + (2 * nb2 + bnb) * 16));
          uint32_t bh[4], bl[4];
          ldsm_x4t(bh, sbase + h3 * 16384 + off);
          ldsm_x4t(bl, sbase + h3 * 16384 + 8192 + off);
          mma_bf16(a0, xh[ks], bh[0], bh[1]);
          mma_bf16(a0, xl[ks], bh[0], bh[1]);
          mma_bf16(a0, xh[ks], bl[0], bl[1]);
          mma_bf16(a1, xh[ks], bh[2], bh[3]);
          mma_bf16(a1, xl[ks], bh[2], bh[3]);
          mma_bf16(a1, xh[ks], bl[2], bl[3]);
        }
      }
    }
    __syncthreads();
  }

  // ---- epilogue: split fp32 accumulators to bf16 hi/lo gmem ----
  const int r2 = r1 + 8;
#pragma unroll
  for (int nb = 0; nb < 24; ++nb) {
    const int h3 = nb >> 3, col = (nb & 7) * 8 + tg * 2;
    __nv_bfloat16* hp = (h3 == 0) ? g_qh : (h3 == 1) ? g_kh : g_vh;
    __nv_bfloat16* lp = (h3 == 0) ? g_ql : (h3 == 1) ? g_kl : g_vl;
    uint32_t h, l;
    split_pack(acc[nb][0], acc[nb][1], h, l);
    *(uint32_t*)(hp + (size_t)r1 * kHD + col) = h;
    *(uint32_t*)(lp + (size_t)r1 * kHD + col) = l;
    split_pack(acc[nb][2], acc[nb][3], h, l);
    *(uint32_t*)(hp + (size_t)r2 * kHD + col) = h;
    *(uint32_t*)(lp + (size_t)r2 * kHD + col) = l;
  }
}

// ---------------------------------------------------------------------------
// Kernel 2: FA2-style causal flash attention, cp.async double-buffered K/V.
// grid = (64, 4), block = 128 (4 warps x 16 query rows); 64-key tiles.
// ---------------------------------------------------------------------------
namespace {
constexpr int kvStage = 32768;        // kh 0, kl 8192, vh 16384, vl 24576
constexpr int aQH = 65536, aQL = 73728;
constexpr int aMADD = 81920;          // 2 slots x 256B
constexpr int kAttnSmem = 82432;
}

__global__ __launch_bounds__(128) void attn_kernel(
    const int* __restrict__ pmask, float* __restrict__ out) {
  extern __shared__ char smem[];
  const uint32_t sb = smem_u32(smem);
  const int tid = threadIdx.x;
  const int w = tid >> 5, lane = tid & 31;
  const int g = lane >> 2, tg = lane & 3;
  const int b = blockIdx.y;
  const int qi = (gridDim.x - 1) - blockIdx.x;  // heavy tiles first
  const int t0 = qi * 64;
  const int qg1 = t0 + w * 16 + g;
  const int qg2 = qg1 + 8;
  const int ntiles = qi + 1;

  auto issue_kv = [&](int s0n, int stage) {
    const uint32_t sbase = sb + stage * kvStage;
#pragma unroll
    for (int rep = 0; rep < 16; ++rep) {
      const int e = tid + rep * 128;
      const int which = e >> 9, rem = e & 511;
      const int j = rem >> 3, ch = rem & 7;
      const __nv_bfloat16* base =
          (which == 0) ? g_kh : (which == 1) ? g_kl : (which == 2) ? g_vh : g_vl;
      cp16(sbase + which * 8192 + sw128(j * 128 + ch * 16),
           base + (size_t)(b * kT + s0n + j) * kHD + ch * 8);
    }
    if (tid < 64)
      ((float*)(smem + aMADD + stage * 256))[tid] =
          (pmask[b * kT + s0n + tid] == 0) ? kNegBig : 0.0f;
    CP_COMMIT();
  };

  issue_kv(0, 0);

  // ---- stage Q tile (hi/lo) and build resident fragments ----
#pragma unroll
  for (int rep = 0; rep < 4; ++rep) {
    const int e = tid + rep * 128;
    const int j = e >> 3, ch = e & 7;
    const uint32_t sw = sw128((uint32_t)(j * 128 + ch * 16));
    const size_t goff = (size_t)(b * kT + t0 + j) * kHD + ch * 8;
    *(uint4*)(smem + aQH + sw) = *(const uint4*)(g_qh + goff);
    *(uint4*)(smem + aQL + sw) = *(const uint4*)(g_ql + goff);
  }
  __syncthreads();
  uint32_t qh[4][4], ql[4][4];
  {
    const int arow = w * 16 + (lane & 15);
    const int acb = lane >> 4;
#pragma unroll
    for (int ks = 0; ks < 4; ++ks) {
      const uint32_t off = sw128((uint32_t)(arow * 128 + ks * 32 + acb * 16));
      ldsm_x4(qh[ks], sb + aQH + off);
      ldsm_x4(ql[ks], sb + aQL + off);
    }
  }

  float O[8][4] = {};
  float m1 = kNegBig, m2 = kNegBig, l1 = 0.0f, l2 = 0.0f;
  // per-lane x4 address parts
  const int krow = lane & 7;                 // K: matrix row within j-tile
  const int kk8 = ((lane >> 3) & 1) * 16;    // K: k-half byte offset
  const int kjb = lane >> 4;                 // K: which j-tile of the pair
  const int vrow = (lane & 7) + ((lane >> 3) & 1) * 8;  // V: key row
  const int vnb = lane >> 4;                 // V: which n-tile of the pair

  for (int it = 0; it < ntiles; ++it) {
    const int s0 = it * 64;
    if (it + 1 < ntiles) { issue_kv(s0 + 64, (it + 1) & 1); CP_WAIT(1); }
    else CP_WAIT(0);
    __syncthreads();
    const uint32_t sbase = sb + (it & 1) * kvStage;
    const float* madd = (const float*)(smem + aMADD + (it & 1) * 256);

    // ---- S = Q K^T (3-pass split, x4 K loads) ----
    float sc[8][4];
#pragma unroll
    for (int jb2 = 0; jb2 < 4; ++jb2) {
      float* s0p = sc[2 * jb2];
      float* s1p = sc[2 * jb2 + 1];
      s0p[0] = s0p[1] = s0p[2] = s0p[3] = 0.0f;
      s1p[0] = s1p[1] = s1p[2] = s1p[3] = 0.0f;
#pragma unroll
      for (int ks = 0; ks < 4; ++ks) {
        const uint32_t off = sw128(
            (uint32_t)(((2 * jb2 + kjb) * 8 + krow) * 128 + ks * 32 + kk8));
        uint32_t kh4[4], kl4[4];
        ldsm_x4(kh4, sbase + off);
        ldsm_x4(kl4, sbase + 8192 + off);
        mma_bf16(s0p, qh[ks], kh4[0], kh4[1]);
        mma_bf16(s0p, ql[ks], kh4[0], kh4[1]);
        mma_bf16(s0p, qh[ks], kl4[0], kl4[1]);
        mma_bf16(s1p, qh[ks], kh4[2], kh4[3]);
        mma_bf16(s1p, ql[ks], kh4[2], kh4[3]);
        mma_bf16(s1p, qh[ks], kl4[2], kl4[3]);
      }
    }

    // ---- masked online softmax ----
    const bool diag = (it == ntiles - 1);
    float mx1 = kNegBig, mx2 = kNegBig;
#pragma unroll
    for (int jb = 0; jb < 8; ++jb) {
#pragma unroll
      for (int i = 0; i < 2; ++i) {
        const int jl = jb * 8 + tg * 2 + i;
        const float ma = madd[jl];
        float v1 = sc[jb][i] * kScale + ma;
        float v2 = sc[jb][2 + i] * kScale + ma;
        if (diag) {
          const int jglob = s0 + jl;
          if (jglob > qg1) v1 = kNegBig;
          if (jglob > qg2) v2 = kNegBig;
        }
        sc[jb][i] = v1;
        sc[jb][2 + i] = v2;
        mx1 = fmaxf(mx1, v1);
        mx2 = fmaxf(mx2, v2);
      }
    }
    mx1 = fmaxf(mx1, __shfl_xor_sync(0xffffffffu, mx1, 1));
    mx1 = fmaxf(mx1, __shfl_xor_sync(0xffffffffu, mx1, 2));
    mx2 = fmaxf(mx2, __shfl_xor_sync(0xffffffffu, mx2, 1));
    mx2 = fmaxf(mx2, __shfl_xor_sync(0xffffffffu, mx2, 2));
    const float mn1 = fmaxf(m1, mx1), mn2 = fmaxf(m2, mx2);
    const float al1 = __expf(m1 - mn1), al2 = __expf(m2 - mn2);
    m1 = mn1; m2 = mn2;
    float s1 = 0.0f, s2 = 0.0f;
#pragma unroll
    for (int jb = 0; jb < 8; ++jb) {
      sc[jb][0] = __expf(sc[jb][0] - mn1);
      sc[jb][1] = __expf(sc[jb][1] - mn1);
      sc[jb][2] = __expf(sc[jb][2] - mn2);
      sc[jb][3] = __expf(sc[jb][3] - mn2);
      s1 += sc[jb][0] + sc[jb][1];
      s2 += sc[jb][2] + sc[jb][3];
    }
    s1 += __shfl_xor_sync(0xffffffffu, s1, 1);
    s1 += __shfl_xor_sync(0xffffffffu, s1, 2);
    s2 += __shfl_xor_sync(0xffffffffu, s2, 1);
    s2 += __shfl_xor_sync(0xffffffffu, s2, 2);
    l1 = l1 * al1 + s1;
    l2 = l2 * al2 + s2;
#pragma unroll
    for (int nb = 0; nb < 8; ++nb) {
      O[nb][0] *= al1; O[nb][1] *= al1;
      O[nb][2] *= al2; O[nb][3] *= al2;
    }

    // ---- P C-frag -> A-frag (hi/lo) in registers ----
    uint32_t ph[4][4], pl[4][4];
#pragma unroll
    for (int ks = 0; ks < 4; ++ks) {
      const int jb0 = 2 * ks, jb1 = 2 * ks + 1;
      split_pack(sc[jb0][0], sc[jb0][1], ph[ks][0], pl[ks][0]);
      split_pack(sc[jb0][2], sc[jb0][3], ph[ks][1], pl[ks][1]);
      split_pack(sc[jb1][0], sc[jb1][1], ph[ks][2], pl[ks][2]);
      split_pack(sc[jb1][2], sc[jb1][3], ph[ks][3], pl[ks][3]);
    }

    // ---- O += P V (3-pass split, x4 trans V loads) ----
#pragma unroll
    for (int nb2 = 0; nb2 < 4; ++nb2) {
      float* o0 = O[2 * nb2];
      float* o1 = O[2 * nb2 + 1];
#pragma unroll
      for (int ks = 0; ks < 4; ++ks) {
        const uint32_t off = sw128(
            (uint32_t)((ks * 16 + vrow) * 128 + (2 * nb2 + vnb) * 16));
        uint32_t vh4[4], vl4[4];
        ldsm_x4t(vh4, sbase + 16384 + off);
        ldsm_x4t(vl4, sbase + 24576 + off);
        mma_bf16(o0, ph[ks], vh4[0], vh4[1]);
        mma_bf16(o0, pl[ks], vh4[0], vh4[1]);
        mma_bf16(o0, ph[ks], vl4[0], vl4[1]);
        mma_bf16(o1, ph[ks], vh4[2], vh4[3]);
        mma_bf16(o1, pl[ks], vh4[2], vh4[3]);
        mma_bf16(o1, ph[ks], vl4[2], vl4[3]);
      }
    }
    __syncthreads();
  }

  // ---- epilogue ----
  const float inv1 = 1.0f / l1, inv2 = 1.0f / l2;
  const size_t r1 = (size_t)(b * kT + qg1) * kHD;
  const size_t r2 = (size_t)(b * kT + qg2) * kHD;
#pragma unroll
  for (int nb = 0; nb < 8; ++nb) {
    const int col = nb * 8 + tg * 2;
    *(float2*)(out + r1 + col) = make_float2(O[nb][0] * inv1, O[nb][1] * inv1);
    *(float2*)(out + r2 + col) = make_float2(O[nb][2] * inv2, O[nb][3] * inv2);
  }
}

// ---------------------------------------------------------------------------
extern "C" void kernel_launch(void* const* d_in, const int* in_sizes, int n_in,
                              void* d_out, int out_size) {
  const float* x  = (const float*)d_in[0];
  const float* Wq = (const float*)d_in[1];
  const float* Wk = (const float*)d_in[2];
  const float* Wv = (const float*)d_in[3];
  const int*   pm = (const int*)d_in[4];
  float* out = (float*)d_out;

  cudaFuncSetAttribute(proj_kernel, cudaFuncAttributeMaxDynamicSharedMemorySize,
                       kProjSmem);
  cudaFuncSetAttribute(attn_kernel, cudaFuncAttributeMaxDynamicSharedMemorySize,
                       kAttnSmem);

  wsplit_kernel<<<192, 256>>>(Wq, Wk, Wv);
  proj_kernel<<<kM / 64, 128, kProjSmem>>>(x);
  attn_kernel<<<dim3(64, kB), 128, kAttnSmem>>>(pm, out);
}

// round 7
// speedup vs baseline: 4.9208x; 1.3791x over previous
#include <cuda_runtime.h>
#include <cuda_bf16.h>
#include <cstdint>

// Problem constants
namespace {
constexpr int kB  = 4;
constexpr int kT  = 4096;
constexpr int kC  = 1024;
constexpr int kHD = 64;
constexpr int kM  = kB * kT;            // 16384 rows
constexpr float kScale  = 0.125f;       // 1/sqrt(64)
constexpr float kNegBig = -1e30f;
}

// bf16 hi/lo split operands (all row-major [t][64])
__device__ __nv_bfloat16 g_qh[kM * kHD];
__device__ __nv_bfloat16 g_ql[kM * kHD];
__device__ __nv_bfloat16 g_kh[kM * kHD];
__device__ __nv_bfloat16 g_kl[kM * kHD];
__device__ __nv_bfloat16 g_vh[kM * kHD];
__device__ __nv_bfloat16 g_vl[kM * kHD];
// Pre-split weights [3][1024][64]
__device__ __nv_bfloat16 g_wh[3 * kC * kHD];
__device__ __nv_bfloat16 g_wl[3 * kC * kHD];

// ---------------------------------------------------------------------------
// Helpers
// ---------------------------------------------------------------------------
__device__ __forceinline__ uint32_t smem_u32(const void* p) {
  uint32_t a;
  asm("{ .reg .u64 t; cvta.to.shared.u64 t, %1; cvt.u32.u64 %0, t; }"
      : "=r"(a) : "l"(p));
  return a;
}
__device__ __forceinline__ uint32_t sw128(uint32_t off) {
  return off ^ ((off >> 3) & 0x70);
}
__device__ __forceinline__ void mma_bf16(float c[4], const uint32_t a[4],
                                         uint32_t b0, uint32_t b1) {
  asm volatile(
      "mma.sync.aligned.m16n8k16.row.col.f32.bf16.bf16.f32 "
      "{%0,%1,%2,%3}, {%4,%5,%6,%7}, {%8,%9}, {%0,%1,%2,%3};"
      : "+f"(c[0]), "+f"(c[1]), "+f"(c[2]), "+f"(c[3])
      : "r"(a[0]), "r"(a[1]), "r"(a[2]), "r"(a[3]), "r"(b0), "r"(b1));
}
__device__ __forceinline__ void ldsm_x4(uint32_t r[4], uint32_t addr) {
  asm volatile("ldmatrix.sync.aligned.m8n8.x4.shared.b16 {%0,%1,%2,%3}, [%4];"
               : "=r"(r[0]), "=r"(r[1]), "=r"(r[2]), "=r"(r[3]) : "r"(addr));
}
__device__ __forceinline__ void ldsm_x4t(uint32_t r[4], uint32_t addr) {
  asm volatile("ldmatrix.sync.aligned.m8n8.x4.trans.shared.b16 {%0,%1,%2,%3}, [%4];"
               : "=r"(r[0]), "=r"(r[1]), "=r"(r[2]), "=r"(r[3]) : "r"(addr));
}
__device__ __forceinline__ void cp16(uint32_t dst, const void* src) {
  asm volatile("cp.async.cg.shared.global [%0], [%1], 16;" :: "r"(dst),
               "l"(__cvta_generic_to_global(src)));
}
#define CP_COMMIT() asm volatile("cp.async.commit_group;" ::: "memory")
#define CP_WAIT(n)  asm volatile("cp.async.wait_group %0;" :: "n"(n) : "memory")
__device__ __forceinline__ void barteam(int id) {
  asm volatile("bar.sync %0, 128;" :: "r"(id) : "memory");
}

// Pack two fp32 into bf16x2 (lower half = a0) plus the residual bf16x2.
__device__ __forceinline__ void split_pack(float a0, float a1, uint32_t& h,
                                           uint32_t& l) {
  asm("cvt.rn.bf16x2.f32 %0, %1, %2;" : "=r"(h) : "f"(a1), "f"(a0));
  float f0 = __uint_as_float(h << 16);
  float f1 = __uint_as_float(h & 0xFFFF0000u);
  asm("cvt.rn.bf16x2.f32 %0, %1, %2;" : "=r"(l) : "f"(a1 - f1), "f"(a0 - f0));
}

// ---------------------------------------------------------------------------
// Kernel 0: W pre-split (fp32 -> bf16 hi/lo). grid=192, block=256.
// ---------------------------------------------------------------------------
__global__ __launch_bounds__(256) void wsplit_kernel(
    const float* __restrict__ Wq, const float* __restrict__ Wk,
    const float* __restrict__ Wv) {
  int p = blockIdx.x * 256 + threadIdx.x;
#pragma unroll
  for (int rep = 0; rep < 2; ++rep, p += 49152) {
    const int h3 = p >> 15;          // 32768 float2 per head
    const int rem = p & 32767;
    const float* W = (h3 == 0) ? Wq : (h3 == 1) ? Wk : Wv;
    float2 wv = *(const float2*)&W[rem * 2];
    uint32_t h, l;
    split_pack(wv.x, wv.y, h, l);
    *(uint32_t*)(g_wh + (size_t)h3 * kC * kHD + rem * 2) = h;
    *(uint32_t*)(g_wl + (size_t)h3 * kC * kHD + rem * 2) = l;
  }
}

// ---------------------------------------------------------------------------
// Kernel 1: QKV projection. grid = kM/64, block = 128 (unchanged from R6).
// ---------------------------------------------------------------------------
namespace {
constexpr int kProjStage = 49152;
constexpr int kProjSmem  = 2 * kProjStage;
}

__global__ __launch_bounds__(128) void proj_kernel(const float* __restrict__ x) {
  extern __shared__ char smem[];
  const uint32_t sb = smem_u32(smem);
  const int tid = threadIdx.x;
  const int w = tid >> 5, lane = tid & 31;
  const int g = lane >> 2, tg = lane & 3;
  const int row0 = blockIdx.x * 64;
  const int brow = (lane & 7) + ((lane >> 3) & 1) * 8;
  const int bnb = lane >> 4;

  auto issue_w = [&](int kc, int stage) {
    const uint32_t sbase = sb + stage * kProjStage;
#pragma unroll
    for (int rep = 0; rep < 24; ++rep) {
      const int e = tid + rep * 128;
      const int ch = e & 7, row = (e >> 3) & 63, rest = e >> 9;
      const int h3 = rest >> 1, hl = rest & 1;
      const __nv_bfloat16* src = (hl ? g_wl : g_wh) +
          ((size_t)h3 * kC + kc * 64 + row) * kHD + ch * 8;
      cp16(sbase + h3 * 16384 + hl * 8192 + sw128(row * 128 + ch * 16), src);
    }
    CP_COMMIT();
  };

  float acc[24][4] = {};
  issue_w(0, 0);

  const int r1 = row0 + w * 16 + g;
  for (int kc = 0; kc < 16; ++kc) {
    uint32_t xh[4][4], xl[4][4];
#pragma unroll
    for (int ks = 0; ks < 4; ++ks) {
      const float* p1 = x + (size_t)r1 * kC + kc * 64 + ks * 16 + tg * 2;
      const float* p2 = p1 + (size_t)8 * kC;
      float2 v00 = *(const float2*)p1;
      float2 v10 = *(const float2*)p2;
      float2 v01 = *(const float2*)(p1 + 8);
      float2 v11 = *(const float2*)(p2 + 8);
      split_pack(v00.x, v00.y, xh[ks][0], xl[ks][0]);
      split_pack(v10.x, v10.y, xh[ks][1], xl[ks][1]);
      split_pack(v01.x, v01.y, xh[ks][2], xl[ks][2]);
      split_pack(v11.x, v11.y, xh[ks][3], xl[ks][3]);
    }
    if (kc < 15) { issue_w(kc + 1, (kc + 1) & 1); CP_WAIT(1); }
    else CP_WAIT(0);
    __syncthreads();

    const uint32_t sbase = sb + (kc & 1) * kProjStage;
#pragma unroll
    for (int h3 = 0; h3 < 3; ++h3) {
#pragma unroll
      for (int nb2 = 0; nb2 < 4; ++nb2) {
        float* a0 = acc[h3 * 8 + 2 * nb2];
        float* a1 = acc[h3 * 8 + 2 * nb2 + 1];
#pragma unroll
        for (int ks = 0; ks < 4; ++ks) {
          const uint32_t off =
              sw128((uint32_t)((ks * 16 + brow) * 128 + (2 * nb2 + bnb) * 16));
          uint32_t bh[4], bl[4];
          ldsm_x4t(bh, sbase + h3 * 16384 + off);
          ldsm_x4t(bl, sbase + h3 * 16384 + 8192 + off);
          mma_bf16(a0, xh[ks], bh[0], bh[1]);
          mma_bf16(a0, xl[ks], bh[0], bh[1]);
          mma_bf16(a0, xh[ks], bl[0], bl[1]);
          mma_bf16(a1, xh[ks], bh[2], bh[3]);
          mma_bf16(a1, xl[ks], bh[2], bh[3]);
          mma_bf16(a1, xh[ks], bl[2], bl[3]);
        }
      }
    }
    __syncthreads();
  }

  const int r2 = r1 + 8;
#pragma unroll
  for (int nb = 0; nb < 24; ++nb) {
    const int h3 = nb >> 3, col = (nb & 7) * 8 + tg * 2;
    __nv_bfloat16* hp = (h3 == 0) ? g_qh : (h3 == 1) ? g_kh : g_vh;
    __nv_bfloat16* lp = (h3 == 0) ? g_ql : (h3 == 1) ? g_kl : g_vl;
    uint32_t h, l;
    split_pack(acc[nb][0], acc[nb][1], h, l);
    *(uint32_t*)(hp + (size_t)r1 * kHD + col) = h;
    *(uint32_t*)(lp + (size_t)r1 * kHD + col) = l;
    split_pack(acc[nb][2], acc[nb][3], h, l);
    *(uint32_t*)(hp + (size_t)r2 * kHD + col) = h;
    *(uint32_t*)(lp + (size_t)r2 * kHD + col) = l;
  }
}

// ---------------------------------------------------------------------------
// Kernel 2: split-K causal flash attention with paired query tiles.
// grid = (32, 4), block = 256 = two 4-warp teams.
// Phase 0: query tile qi = 63-bx; phase 1: qi = bx.
// Within a phase both teams process the same query tile; team t takes key
// tiles it = t, t+2, ... with private double-buffered cp.async K/V.
// Teams merge via log-sum-exp at phase end.
// ---------------------------------------------------------------------------
namespace {
// smem layout (bytes)
constexpr int aKV   = 0;        // team t, stage s: t*65536 + s*32768 (4 x 32KB)
constexpr int aQH   = 131072;   // 8KB
constexpr int aQL   = 139264;   // 8KB
constexpr int aMADD = 147456;   // team t, stage s: t*512 + s*256 (1KB)
constexpr int aM    = 148480;   // m[2][64] floats (512B)
constexpr int aL    = 148992;   // l[2][64] floats (512B)
constexpr int aOSC  = 149504;   // O scratch 64x64 fp32 (16KB)
constexpr int kAttnSmem = 165888;
}

__global__ __launch_bounds__(256) void attn_kernel(
    const int* __restrict__ pmask, float* __restrict__ out) {
  extern __shared__ char smem[];
  const uint32_t sb = smem_u32(smem);
  const int tid = threadIdx.x;
  const int team = tid >> 7;             // 0 or 1
  const int wt = tid & 127;              // team-local thread
  const int w = wt >> 5, lane = wt & 31;
  const int g = lane >> 2, tg = lane & 3;
  const int b = blockIdx.y;
  const int bx = blockIdx.x;
  const int barid = 1 + team;

  // per-lane ldmatrix address parts
  const int krow = lane & 7;
  const int kk8 = ((lane >> 3) & 1) * 16;
  const int kjb = lane >> 4;
  const int vrow = (lane & 7) + ((lane >> 3) & 1) * 8;
  const int vnb = lane >> 4;

  auto issue_kv = [&](int s0n, int stage) {
    const uint32_t sbase = sb + aKV + team * 65536 + stage * 32768;
#pragma unroll
    for (int rep = 0; rep < 16; ++rep) {
      const int e = wt + rep * 128;
      const int which = e >> 9, rem = e & 511;
      const int j = rem >> 3, ch = rem & 7;
      const __nv_bfloat16* base =
          (which == 0) ? g_kh : (which == 1) ? g_kl : (which == 2) ? g_vh : g_vl;
      cp16(sbase + which * 8192 + sw128(j * 128 + ch * 16),
           base + (size_t)(b * kT + s0n + j) * kHD + ch * 8);
    }
    if (wt < 64)
      ((float*)(smem + aMADD + team * 512 + stage * 256))[wt] =
          (pmask[b * kT + s0n + wt] == 0) ? kNegBig : 0.0f;
    CP_COMMIT();
  };

#pragma unroll 1
  for (int phase = 0; phase < 2; ++phase) {
    const int qi = phase ? bx : (63 - bx);
    const int t0 = qi * 64;
    const int ntiles = qi + 1;
    const int qg1 = t0 + w * 16 + g;
    const int qg2 = qg1 + 8;

    __syncthreads();  // previous phase fully done (Q/Oscratch reuse)

    // prefetch this team's first key tile (buffers are team-private & idle)
    if (team < ntiles) issue_kv(team * 64, 0);

    // ---- cooperative Q tile load (hi/lo), all 256 threads ----
#pragma unroll
    for (int rep = 0; rep < 2; ++rep) {
      const int e = tid + rep * 256;
      const int j = e >> 3, ch = e & 7;
      const uint32_t sw = sw128((uint32_t)(j * 128 + ch * 16));
      const size_t goff = (size_t)(b * kT + t0 + j) * kHD + ch * 8;
      *(uint4*)(smem + aQH + sw) = *(const uint4*)(g_qh + goff);
      *(uint4*)(smem + aQL + sw) = *(const uint4*)(g_ql + goff);
    }
    __syncthreads();

    // ---- resident Q fragments ----
    uint32_t qh[4][4], ql[4][4];
    {
      const int arow = w * 16 + (lane & 15);
      const int acb = lane >> 4;
#pragma unroll
      for (int ks = 0; ks < 4; ++ks) {
        const uint32_t off = sw128((uint32_t)(arow * 128 + ks * 32 + acb * 16));
        ldsm_x4(qh[ks], sb + aQH + off);
        ldsm_x4(ql[ks], sb + aQL + off);
      }
    }

    float O[8][4] = {};
    float m1 = kNegBig, m2 = kNegBig, l1 = 0.0f, l2 = 0.0f;

    for (int it = team; it < ntiles; it += 2) {
      const int s0 = it * 64;
      const int ord = it >> 1;
      if (it + 2 < ntiles) { issue_kv((it + 2) * 64, (ord + 1) & 1); CP_WAIT(1); }
      else CP_WAIT(0);
      barteam(barid);
      const uint32_t sbase = sb + aKV + team * 65536 + (ord & 1) * 32768;
      const float* madd =
          (const float*)(smem + aMADD + team * 512 + (ord & 1) * 256);

      // ---- S = Q K^T (3-pass split) ----
      float sc[8][4];
#pragma unroll
      for (int jb2 = 0; jb2 < 4; ++jb2) {
        float* s0p = sc[2 * jb2];
        float* s1p = sc[2 * jb2 + 1];
        s0p[0] = s0p[1] = s0p[2] = s0p[3] = 0.0f;
        s1p[0] = s1p[1] = s1p[2] = s1p[3] = 0.0f;
#pragma unroll
        for (int ks = 0; ks < 4; ++ks) {
          const uint32_t off = sw128(
              (uint32_t)(((2 * jb2 + kjb) * 8 + krow) * 128 + ks * 32 + kk8));
          uint32_t kh4[4], kl4[4];
          ldsm_x4(kh4, sbase + off);
          ldsm_x4(kl4, sbase + 8192 + off);
          mma_bf16(s0p, qh[ks], kh4[0], kh4[1]);
          mma_bf16(s0p, ql[ks], kh4[0], kh4[1]);
          mma_bf16(s0p, qh[ks], kl4[0], kl4[1]);
          mma_bf16(s1p, qh[ks], kh4[2], kh4[3]);
          mma_bf16(s1p, ql[ks], kh4[2], kh4[3]);
          mma_bf16(s1p, qh[ks], kl4[2], kl4[3]);
        }
      }

      // ---- masked online softmax ----
      const bool diag = (it == ntiles - 1);
      float mx1 = kNegBig, mx2 = kNegBig;
#pragma unroll
      for (int jb = 0; jb < 8; ++jb) {
#pragma unroll
        for (int i = 0; i < 2; ++i) {
          const int jl = jb * 8 + tg * 2 + i;
          const float ma = madd[jl];
          float v1 = sc[jb][i] * kScale + ma;
          float v2 = sc[jb][2 + i] * kScale + ma;
          if (diag) {
            const int jglob = s0 + jl;
            if (jglob > qg1) v1 = kNegBig;
            if (jglob > qg2) v2 = kNegBig;
          }
          sc[jb][i] = v1;
          sc[jb][2 + i] = v2;
          mx1 = fmaxf(mx1, v1);
          mx2 = fmaxf(mx2, v2);
        }
      }
      mx1 = fmaxf(mx1, __shfl_xor_sync(0xffffffffu, mx1, 1));
      mx1 = fmaxf(mx1, __shfl_xor_sync(0xffffffffu, mx1, 2));
      mx2 = fmaxf(mx2, __shfl_xor_sync(0xffffffffu, mx2, 1));
      mx2 = fmaxf(mx2, __shfl_xor_sync(0xffffffffu, mx2, 2));
      const float mn1 = fmaxf(m1, mx1), mn2 = fmaxf(m2, mx2);
      const float al1 = __expf(m1 - mn1), al2 = __expf(m2 - mn2);
      m1 = mn1; m2 = mn2;
      float s1 = 0.0f, s2 = 0.0f;
#pragma unroll
      for (int jb = 0; jb < 8; ++jb) {
        sc[jb][0] = __expf(sc[jb][0] - mn1);
        sc[jb][1] = __expf(sc[jb][1] - mn1);
        sc[jb][2] = __expf(sc[jb][2] - mn2);
        sc[jb][3] = __expf(sc[jb][3] - mn2);
        s1 += sc[jb][0] + sc[jb][1];
        s2 += sc[jb][2] + sc[jb][3];
      }
      s1 += __shfl_xor_sync(0xffffffffu, s1, 1);
      s1 += __shfl_xor_sync(0xffffffffu, s1, 2);
      s2 += __shfl_xor_sync(0xffffffffu, s2, 1);
      s2 += __shfl_xor_sync(0xffffffffu, s2, 2);
      l1 = l1 * al1 + s1;
      l2 = l2 * al2 + s2;
#pragma unroll
      for (int nb = 0; nb < 8; ++nb) {
        O[nb][0] *= al1; O[nb][1] *= al1;
        O[nb][2] *= al2; O[nb][3] *= al2;
      }

      // ---- P C-frag -> A-frag (hi/lo) ----
      uint32_t ph[4][4], pl[4][4];
#pragma unroll
      for (int ks = 0; ks < 4; ++ks) {
        const int jb0 = 2 * ks, jb1 = 2 * ks + 1;
        split_pack(sc[jb0][0], sc[jb0][1], ph[ks][0], pl[ks][0]);
        split_pack(sc[jb0][2], sc[jb0][3], ph[ks][1], pl[ks][1]);
        split_pack(sc[jb1][0], sc[jb1][1], ph[ks][2], pl[ks][2]);
        split_pack(sc[jb1][2], sc[jb1][3], ph[ks][3], pl[ks][3]);
      }

      // ---- O += P V (3-pass split) ----
#pragma unroll
      for (int nb2 = 0; nb2 < 4; ++nb2) {
        float* o0 = O[2 * nb2];
        float* o1 = O[2 * nb2 + 1];
#pragma unroll
        for (int ks = 0; ks < 4; ++ks) {
          const uint32_t off = sw128(
              (uint32_t)((ks * 16 + vrow) * 128 + (2 * nb2 + vnb) * 16));
          uint32_t vh4[4], vl4[4];
          ldsm_x4t(vh4, sbase + 16384 + off);
          ldsm_x4t(vl4, sbase + 24576 + off);
          mma_bf16(o0, ph[ks], vh4[0], vh4[1]);
          mma_bf16(o0, pl[ks], vh4[0], vh4[1]);
          mma_bf16(o0, ph[ks], vl4[0], vl4[1]);
          mma_bf16(o1, ph[ks], vh4[2], vh4[3]);
          mma_bf16(o1, pl[ks], vh4[2], vh4[3]);
          mma_bf16(o1, ph[ks], vl4[2], vl4[3]);
        }
      }
      barteam(barid);  // all team reads of this stage done before its reuse
    }

    // ---- team merge (log-sum-exp) ----
    const int rl1 = w * 16 + g, rl2 = rl1 + 8;
    float* mA = (float*)(smem + aM);
    float* lA = (float*)(smem + aL);
    if (tg == 0) {
      mA[team * 64 + rl1] = m1; mA[team * 64 + rl2] = m2;
      lA[team * 64 + rl1] = l1; lA[team * 64 + rl2] = l2;
    }
    __syncthreads();
    const float mo1 = mA[(1 - team) * 64 + rl1];
    const float mo2 = mA[(1 - team) * 64 + rl2];
    const float lo1 = lA[(1 - team) * 64 + rl1];
    const float lo2 = lA[(1 - team) * 64 + rl2];
    const float M1 = fmaxf(m1, mo1), M2 = fmaxf(m2, mo2);
    const float a1 = __expf(m1 - M1), a2 = __expf(m2 - M2);
    const float ao1 = __expf(mo1 - M1), ao2 = __expf(mo2 - M2);
    const float L1 = l1 * a1 + lo1 * ao1;
    const float L2 = l2 * a2 + lo2 * ao2;
    float* osc = (float*)(smem + aOSC);
    if (team == 1) {
#pragma unroll
      for (int nb = 0; nb < 8; ++nb) {
        const int col = nb * 8 + tg * 2;
        osc[rl1 * 64 + col] = O[nb][0] * a1;
        osc[rl1 * 64 + col + 1] = O[nb][1] * a1;
        osc[rl2 * 64 + col] = O[nb][2] * a2;
        osc[rl2 * 64 + col + 1] = O[nb][3] * a2;
      }
    }
    __syncthreads();
    if (team == 0) {
      const float i1 = 1.0f / L1, i2 = 1.0f / L2;
      const size_t r1o = (size_t)(b * kT + qg1) * kHD;
      const size_t r2o = (size_t)(b * kT + qg2) * kHD;
#pragma unroll
      for (int nb = 0; nb < 8; ++nb) {
        const int col = nb * 8 + tg * 2;
        *(float2*)(out + r1o + col) = make_float2(
            (O[nb][0] * a1 + osc[rl1 * 64 + col]) * i1,
            (O[nb][1] * a1 + osc[rl1 * 64 + col + 1]) * i1);
        *(float2*)(out + r2o + col) = make_float2(
            (O[nb][2] * a2 + osc[rl2 * 64 + col]) * i2,
            (O[nb][3] * a2 + osc[rl2 * 64 + col + 1]) * i2);
      }
    }
  }
}

// ---------------------------------------------------------------------------
extern "C" void kernel_launch(void* const* d_in, const int* in_sizes, int n_in,
                              void* d_out, int out_size) {
  const float* x  = (const float*)d_in[0];
  const float* Wq = (const float*)d_in[1];
  const float* Wk = (const float*)d_in[2];
  const float* Wv = (const float*)d_in[3];
  const int*   pm = (const int*)d_in[4];
  float* out = (float*)d_out;

  cudaFuncSetAttribute(proj_kernel, cudaFuncAttributeMaxDynamicSharedMemorySize,
                       kProjSmem);
  cudaFuncSetAttribute(attn_kernel, cudaFuncAttributeMaxDynamicSharedMemorySize,
                       kAttnSmem);

  wsplit_kernel<<<192, 256>>>(Wq, Wk, Wv);
  proj_kernel<<<kM / 64, 128, kProjSmem>>>(x);
  attn_kernel<<<dim3(32, kB), 256, kAttnSmem>>>(pm, out);
}

// round 8
// speedup vs baseline: 5.1164x; 1.0398x over previous
#include <cuda_runtime.h>
#include <cuda_bf16.h>
#include <cstdint>

// Problem constants
namespace {
constexpr int kB  = 4;
constexpr int kT  = 4096;
constexpr int kC  = 1024;
constexpr int kHD = 64;
constexpr int kM  = kB * kT;            // 16384 rows
constexpr float kScale  = 0.125f;       // 1/sqrt(64)
constexpr float kNegBig = -1e30f;
}

// bf16 hi/lo split operands (all row-major [t][64])
__device__ __nv_bfloat16 g_qh[kM * kHD];
__device__ __nv_bfloat16 g_ql[kM * kHD];
__device__ __nv_bfloat16 g_kh[kM * kHD];
__device__ __nv_bfloat16 g_kl[kM * kHD];
__device__ __nv_bfloat16 g_vh[kM * kHD];
__device__ __nv_bfloat16 g_vl[kM * kHD];
// Pre-split weights [3][1024][64]
__device__ __nv_bfloat16 g_wh[3 * kC * kHD];
__device__ __nv_bfloat16 g_wl[3 * kC * kHD];

// ---------------------------------------------------------------------------
// Helpers
// ---------------------------------------------------------------------------
__device__ __forceinline__ uint32_t smem_u32(const void* p) {
  uint32_t a;
  asm("{ .reg .u64 t; cvta.to.shared.u64 t, %1; cvt.u32.u64 %0, t; }"
      : "=r"(a) : "l"(p));
  return a;
}
__device__ __forceinline__ uint32_t sw128(uint32_t off) {
  return off ^ ((off >> 3) & 0x70);
}
__device__ __forceinline__ void mma_bf16(float c[4], const uint32_t a[4],
                                         uint32_t b0, uint32_t b1) {
  asm volatile(
      "mma.sync.aligned.m16n8k16.row.col.f32.bf16.bf16.f32 "
      "{%0,%1,%2,%3}, {%4,%5,%6,%7}, {%8,%9}, {%0,%1,%2,%3};"
      : "+f"(c[0]), "+f"(c[1]), "+f"(c[2]), "+f"(c[3])
      : "r"(a[0]), "r"(a[1]), "r"(a[2]), "r"(a[3]), "r"(b0), "r"(b1));
}
__device__ __forceinline__ void ldsm_x4(uint32_t r[4], uint32_t addr) {
  asm volatile("ldmatrix.sync.aligned.m8n8.x4.shared.b16 {%0,%1,%2,%3}, [%4];"
               : "=r"(r[0]), "=r"(r[1]), "=r"(r[2]), "=r"(r[3]) : "r"(addr));
}
__device__ __forceinline__ void ldsm_x4t(uint32_t r[4], uint32_t addr) {
  asm volatile("ldmatrix.sync.aligned.m8n8.x4.trans.shared.b16 {%0,%1,%2,%3}, [%4];"
               : "=r"(r[0]), "=r"(r[1]), "=r"(r[2]), "=r"(r[3]) : "r"(addr));
}
__device__ __forceinline__ void cp16(uint32_t dst, const void* src) {
  asm volatile("cp.async.cg.shared.global [%0], [%1], 16;" :: "r"(dst),
               "l"(__cvta_generic_to_global(src)));
}
#define CP_COMMIT() asm volatile("cp.async.commit_group;" ::: "memory")
#define CP_WAIT(n)  asm volatile("cp.async.wait_group %0;" :: "n"(n) : "memory")
__device__ __forceinline__ void barteam(int id) {
  asm volatile("bar.sync %0, 128;" :: "r"(id) : "memory");
}

// Pack two fp32 into bf16x2 (lower half = a0) plus the residual bf16x2.
__device__ __forceinline__ void split_pack(float a0, float a1, uint32_t& h,
                                           uint32_t& l) {
  asm("cvt.rn.bf16x2.f32 %0, %1, %2;" : "=r"(h) : "f"(a1), "f"(a0));
  float f0 = __uint_as_float(h << 16);
  float f1 = __uint_as_float(h & 0xFFFF0000u);
  asm("cvt.rn.bf16x2.f32 %0, %1, %2;" : "=r"(l) : "f"(a1 - f1), "f"(a0 - f0));
}

// ---------------------------------------------------------------------------
// Kernel 0: W pre-split (fp32 -> bf16 hi/lo). grid=192, block=256.
// ---------------------------------------------------------------------------
__global__ __launch_bounds__(256) void wsplit_kernel(
    const float* __restrict__ Wq, const float* __restrict__ Wk,
    const float* __restrict__ Wv) {
  int p = blockIdx.x * 256 + threadIdx.x;
#pragma unroll
  for (int rep = 0; rep < 2; ++rep, p += 49152) {
    const int h3 = p >> 15;          // 32768 float2 per head
    const int rem = p & 32767;
    const float* W = (h3 == 0) ? Wq : (h3 == 1) ? Wk : Wv;
    float2 wv = *(const float2*)&W[rem * 2];
    uint32_t h, l;
    split_pack(wv.x, wv.y, h, l);
    *(uint32_t*)(g_wh + (size_t)h3 * kC * kHD + rem * 2) = h;
    *(uint32_t*)(g_wl + (size_t)h3 * kC * kHD + rem * 2) = l;
  }
}

// ---------------------------------------------------------------------------
// Kernel 1: QKV projection. grid = kM/128, block = 256 (8 warps x 16 rows).
// 3-stage cp.async W ring, ONE barrier per k-chunk, x raw-prefetch in regs.
// ---------------------------------------------------------------------------
namespace {
constexpr int kProjStage = 49152;            // 6 tiles x 8KB (3 heads x hi/lo)
constexpr int kProjSmem  = 3 * kProjStage;   // 147456
}

__global__ __launch_bounds__(256, 1) void proj_kernel(const float* __restrict__ x) {
  extern __shared__ char smem[];
  const uint32_t sb = smem_u32(smem);
  const int tid = threadIdx.x;
  const int w = tid >> 5, lane = tid & 31;
  const int g = lane >> 2, tg = lane & 3;
  const int row0 = blockIdx.x * 128;
  const int brow = (lane & 7) + ((lane >> 3) & 1) * 8;
  const int bnb = lane >> 4;

  auto issue_w = [&](int kc, int stage) {
    const uint32_t sbase = sb + stage * kProjStage;
#pragma unroll
    for (int rep = 0; rep < 12; ++rep) {
      const int e = tid + rep * 256;
      const int ch = e & 7, row = (e >> 3) & 63, rest = e >> 9;
      const int h3 = rest >> 1, hl = rest & 1;
      const __nv_bfloat16* src = (hl ? g_wl : g_wh) +
          ((size_t)h3 * kC + kc * 64 + row) * kHD + ch * 8;
      cp16(sbase + h3 * 16384 + hl * 8192 + sw128(row * 128 + ch * 16), src);
    }
    CP_COMMIT();
  };

  const int r1 = row0 + w * 16 + g;
  const float* xrow1 = x + (size_t)r1 * kC + tg * 2;
  const float* xrow2 = xrow1 + (size_t)8 * kC;

  auto load_xraw = [&](float2 xr[16], int kc) {
#pragma unroll
    for (int ks = 0; ks < 4; ++ks) {
      const float* p1 = xrow1 + kc * 64 + ks * 16;
      const float* p2 = xrow2 + kc * 64 + ks * 16;
      xr[ks * 4 + 0] = *(const float2*)p1;
      xr[ks * 4 + 1] = *(const float2*)p2;
      xr[ks * 4 + 2] = *(const float2*)(p1 + 8);
      xr[ks * 4 + 3] = *(const float2*)(p2 + 8);
    }
  };

  float acc[24][4] = {};
  float2 xraw[16];

  issue_w(0, 0);
  issue_w(1, 1);
  load_xraw(xraw, 0);

  int st = 0;
  for (int kc = 0; kc < 16; ++kc) {
    // ---- split current x raw into A fragments; prefetch next raw ----
    uint32_t xh[4][4], xl[4][4];
#pragma unroll
    for (int p = 0; p < 16; ++p)
      split_pack(xraw[p].x, xraw[p].y, xh[p >> 2][p & 3], xl[p >> 2][p & 3]);
    if (kc + 1 < 16) load_xraw(xraw, kc + 1);

    if (kc < 15) CP_WAIT(1); else CP_WAIT(0);
    __syncthreads();

    const uint32_t sbase = sb + st * kProjStage;
#pragma unroll
    for (int h3 = 0; h3 < 3; ++h3) {
#pragma unroll
      for (int nb2 = 0; nb2 < 4; ++nb2) {
        float* a0 = acc[h3 * 8 + 2 * nb2];
        float* a1 = acc[h3 * 8 + 2 * nb2 + 1];
#pragma unroll
        for (int ks = 0; ks < 4; ++ks) {
          const uint32_t off =
              sw128((uint32_t)((ks * 16 + brow) * 128 + (2 * nb2 + bnb) * 16));
          uint32_t bh[4], bl[4];
          ldsm_x4t(bh, sbase + h3 * 16384 + off);
          ldsm_x4t(bl, sbase + h3 * 16384 + 8192 + off);
          mma_bf16(a0, xh[ks], bh[0], bh[1]);
          mma_bf16(a0, xl[ks], bh[0], bh[1]);
          mma_bf16(a0, xh[ks], bl[0], bl[1]);
          mma_bf16(a1, xh[ks], bh[2], bh[3]);
          mma_bf16(a1, xl[ks], bh[2], bh[3]);
          mma_bf16(a1, xh[ks], bl[2], bl[3]);
        }
      }
    }
    // issue stage kc+2 -> (st+2)%3 == (kc-1)%3; its readers cleared the
    // barrier above, so no trailing sync is needed.
    if (kc + 2 < 16) issue_w(kc + 2, (st + 2 >= 3) ? st - 1 : st + 2);
    st = (st + 1 == 3) ? 0 : st + 1;
  }

  // ---- epilogue: split fp32 accumulators to bf16 hi/lo gmem ----
  const int r2 = r1 + 8;
#pragma unroll
  for (int nb = 0; nb < 24; ++nb) {
    const int h3 = nb >> 3, col = (nb & 7) * 8 + tg * 2;
    __nv_bfloat16* hp = (h3 == 0) ? g_qh : (h3 == 1) ? g_kh : g_vh;
    __nv_bfloat16* lp = (h3 == 0) ? g_ql : (h3 == 1) ? g_kl : g_vl;
    uint32_t h, l;
    split_pack(acc[nb][0], acc[nb][1], h, l);
    *(uint32_t*)(hp + (size_t)r1 * kHD + col) = h;
    *(uint32_t*)(lp + (size_t)r1 * kHD + col) = l;
    split_pack(acc[nb][2], acc[nb][3], h, l);
    *(uint32_t*)(hp + (size_t)r2 * kHD + col) = h;
    *(uint32_t*)(lp + (size_t)r2 * kHD + col) = l;
  }
}

// ---------------------------------------------------------------------------
// Kernel 2: split-K causal flash attention with paired query tiles.
// (unchanged from round 7 — verified at 65us / rel_err 1.4e-5)
// ---------------------------------------------------------------------------
namespace {
constexpr int aKV   = 0;
constexpr int aQH   = 131072;
constexpr int aQL   = 139264;
constexpr int aMADD = 147456;
constexpr int aM    = 148480;
constexpr int aL    = 148992;
constexpr int aOSC  = 149504;
constexpr int kAttnSmem = 165888;
}

__global__ __launch_bounds__(256) void attn_kernel(
    const int* __restrict__ pmask, float* __restrict__ out) {
  extern __shared__ char smem[];
  const uint32_t sb = smem_u32(smem);
  const int tid = threadIdx.x;
  const int team = tid >> 7;
  const int wt = tid & 127;
  const int w = wt >> 5, lane = wt & 31;
  const int g = lane >> 2, tg = lane & 3;
  const int b = blockIdx.y;
  const int bx = blockIdx.x;
  const int barid = 1 + team;

  const int krow = lane & 7;
  const int kk8 = ((lane >> 3) & 1) * 16;
  const int kjb = lane >> 4;
  const int vrow = (lane & 7) + ((lane >> 3) & 1) * 8;
  const int vnb = lane >> 4;

  auto issue_kv = [&](int s0n, int stage) {
    const uint32_t sbase = sb + aKV + team * 65536 + stage * 32768;
#pragma unroll
    for (int rep = 0; rep < 16; ++rep) {
      const int e = wt + rep * 128;
      const int which = e >> 9, rem = e & 511;
      const int j = rem >> 3, ch = rem & 7;
      const __nv_bfloat16* base =
          (which == 0) ? g_kh : (which == 1) ? g_kl : (which == 2) ? g_vh : g_vl;
      cp16(sbase + which * 8192 + sw128(j * 128 + ch * 16),
           base + (size_t)(b * kT + s0n + j) * kHD + ch * 8);
    }
    if (wt < 64)
      ((float*)(smem + aMADD + team * 512 + stage * 256))[wt] =
          (pmask[b * kT + s0n + wt] == 0) ? kNegBig : 0.0f;
    CP_COMMIT();
  };

#pragma unroll 1
  for (int phase = 0; phase < 2; ++phase) {
    const int qi = phase ? bx : (63 - bx);
    const int t0 = qi * 64;
    const int ntiles = qi + 1;
    const int qg1 = t0 + w * 16 + g;
    const int qg2 = qg1 + 8;

    __syncthreads();

    if (team < ntiles) issue_kv(team * 64, 0);

#pragma unroll
    for (int rep = 0; rep < 2; ++rep) {
      const int e = tid + rep * 256;
      const int j = e >> 3, ch = e & 7;
      const uint32_t sw = sw128((uint32_t)(j * 128 + ch * 16));
      const size_t goff = (size_t)(b * kT + t0 + j) * kHD + ch * 8;
      *(uint4*)(smem + aQH + sw) = *(const uint4*)(g_qh + goff);
      *(uint4*)(smem + aQL + sw) = *(const uint4*)(g_ql + goff);
    }
    __syncthreads();

    uint32_t qh[4][4], ql[4][4];
    {
      const int arow = w * 16 + (lane & 15);
      const int acb = lane >> 4;
#pragma unroll
      for (int ks = 0; ks < 4; ++ks) {
        const uint32_t off = sw128((uint32_t)(arow * 128 + ks * 32 + acb * 16));
        ldsm_x4(qh[ks], sb + aQH + off);
        ldsm_x4(ql[ks], sb + aQL + off);
      }
    }

    float O[8][4] = {};
    float m1 = kNegBig, m2 = kNegBig, l1 = 0.0f, l2 = 0.0f;

    for (int it = team; it < ntiles; it += 2) {
      const int s0 = it * 64;
      const int ord = it >> 1;
      if (it + 2 < ntiles) { issue_kv((it + 2) * 64, (ord + 1) & 1); CP_WAIT(1); }
      else CP_WAIT(0);
      barteam(barid);
      const uint32_t sbase = sb + aKV + team * 65536 + (ord & 1) * 32768;
      const float* madd =
          (const float*)(smem + aMADD + team * 512 + (ord & 1) * 256);

      float sc[8][4];
#pragma unroll
      for (int jb2 = 0; jb2 < 4; ++jb2) {
        float* s0p = sc[2 * jb2];
        float* s1p = sc[2 * jb2 + 1];
        s0p[0] = s0p[1] = s0p[2] = s0p[3] = 0.0f;
        s1p[0] = s1p[1] = s1p[2] = s1p[3] = 0.0f;
#pragma unroll
        for (int ks = 0; ks < 4; ++ks) {
          const uint32_t off = sw128(
              (uint32_t)(((2 * jb2 + kjb) * 8 + krow) * 128 + ks * 32 + kk8));
          uint32_t kh4[4], kl4[4];
          ldsm_x4(kh4, sbase + off);
          ldsm_x4(kl4, sbase + 8192 + off);
          mma_bf16(s0p, qh[ks], kh4[0], kh4[1]);
          mma_bf16(s0p, ql[ks], kh4[0], kh4[1]);
          mma_bf16(s0p, qh[ks], kl4[0], kl4[1]);
          mma_bf16(s1p, qh[ks], kh4[2], kh4[3]);
          mma_bf16(s1p, ql[ks], kh4[2], kh4[3]);
          mma_bf16(s1p, qh[ks], kl4[2], kl4[3]);
        }
      }

      const bool diag = (it == ntiles - 1);
      float mx1 = kNegBig, mx2 = kNegBig;
#pragma unroll
      for (int jb = 0; jb < 8; ++jb) {
#pragma unroll
        for (int i = 0; i < 2; ++i) {
          const int jl = jb * 8 + tg * 2 + i;
          const float ma = madd[jl];
          float v1 = sc[jb][i] * kScale + ma;
          float v2 = sc[jb][2 + i] * kScale + ma;
          if (diag) {
            const int jglob = s0 + jl;
            if (jglob > qg1) v1 = kNegBig;
            if (jglob > qg2) v2 = kNegBig;
          }
          sc[jb][i] = v1;
          sc[jb][2 + i] = v2;
          mx1 = fmaxf(mx1, v1);
          mx2 = fmaxf(mx2, v2);
        }
      }
      mx1 = fmaxf(mx1, __shfl_xor_sync(0xffffffffu, mx1, 1));
      mx1 = fmaxf(mx1, __shfl_xor_sync(0xffffffffu, mx1, 2));
      mx2 = fmaxf(mx2, __shfl_xor_sync(0xffffffffu, mx2, 1));
      mx2 = fmaxf(mx2, __shfl_xor_sync(0xffffffffu, mx2, 2));
      const float mn1 = fmaxf(m1, mx1), mn2 = fmaxf(m2, mx2);
      const float al1 = __expf(m1 - mn1), al2 = __expf(m2 - mn2);
      m1 = mn1; m2 = mn2;
      float s1 = 0.0f, s2 = 0.0f;
#pragma unroll
      for (int jb = 0; jb < 8; ++jb) {
        sc[jb][0] = __expf(sc[jb][0] - mn1);
        sc[jb][1] = __expf(sc[jb][1] - mn1);
        sc[jb][2] = __expf(sc[jb][2] - mn2);
        sc[jb][3] = __expf(sc[jb][3] - mn2);
        s1 += sc[jb][0] + sc[jb][1];
        s2 += sc[jb][2] + sc[jb][3];
      }
      s1 += __shfl_xor_sync(0xffffffffu, s1, 1);
      s1 += __shfl_xor_sync(0xffffffffu, s1, 2);
      s2 += __shfl_xor_sync(0xffffffffu, s2, 1);
      s2 += __shfl_xor_sync(0xffffffffu, s2, 2);
      l1 = l1 * al1 + s1;
      l2 = l2 * al2 + s2;
#pragma unroll
      for (int nb = 0; nb < 8; ++nb) {
        O[nb][0] *= al1; O[nb][1] *= al1;
        O[nb][2] *= al2; O[nb][3] *= al2;
      }

      uint32_t ph[4][4], pl[4][4];
#pragma unroll
      for (int ks = 0; ks < 4; ++ks) {
        const int jb0 = 2 * ks, jb1 = 2 * ks + 1;
        split_pack(sc[jb0][0], sc[jb0][1], ph[ks][0], pl[ks][0]);
        split_pack(sc[jb0][2], sc[jb0][3], ph[ks][1], pl[ks][1]);
        split_pack(sc[jb1][0], sc[jb1][1], ph[ks][2], pl[ks][2]);
        split_pack(sc[jb1][2], sc[jb1][3], ph[ks][3], pl[ks][3]);
      }

#pragma unroll
      for (int nb2 = 0; nb2 < 4; ++nb2) {
        float* o0 = O[2 * nb2];
        float* o1 = O[2 * nb2 + 1];
#pragma unroll
        for (int ks = 0; ks < 4; ++ks) {
          const uint32_t off = sw128(
              (uint32_t)((ks * 16 + vrow) * 128 + (2 * nb2 + vnb) * 16));
          uint32_t vh4[4], vl4[4];
          ldsm_x4t(vh4, sbase + 16384 + off);
          ldsm_x4t(vl4, sbase + 24576 + off);
          mma_bf16(o0, ph[ks], vh4[0], vh4[1]);
          mma_bf16(o0, pl[ks], vh4[0], vh4[1]);
          mma_bf16(o0, ph[ks], vl4[0], vl4[1]);
          mma_bf16(o1, ph[ks], vh4[2], vh4[3]);
          mma_bf16(o1, pl[ks], vh4[2], vh4[3]);
          mma_bf16(o1, ph[ks], vl4[2], vl4[3]);
        }
      }
      barteam(barid);
    }

    // ---- team merge (log-sum-exp) ----
    const int rl1 = w * 16 + g, rl2 = rl1 + 8;
    float* mA = (float*)(smem + aM);
    float* lA = (float*)(smem + aL);
    if (tg == 0) {
      mA[team * 64 + rl1] = m1; mA[team * 64 + rl2] = m2;
      lA[team * 64 + rl1] = l1; lA[team * 64 + rl2] = l2;
    }
    __syncthreads();
    const float mo1 = mA[(1 - team) * 64 + rl1];
    const float mo2 = mA[(1 - team) * 64 + rl2];
    const float lo1 = lA[(1 - team) * 64 + rl1];
    const float lo2 = lA[(1 - team) * 64 + rl2];
    const float M1 = fmaxf(m1, mo1), M2 = fmaxf(m2, mo2);
    const float a1 = __expf(m1 - M1), a2 = __expf(m2 - M2);
    const float ao1 = __expf(mo1 - M1), ao2 = __expf(mo2 - M2);
    const float L1 = l1 * a1 + lo1 * ao1;
    const float L2 = l2 * a2 + lo2 * ao2;
    float* osc = (float*)(smem + aOSC);
    if (team == 1) {
#pragma unroll
      for (int nb = 0; nb < 8; ++nb) {
        const int col = nb * 8 + tg * 2;
        osc[rl1 * 64 + col] = O[nb][0] * a1;
        osc[rl1 * 64 + col + 1] = O[nb][1] * a1;
        osc[rl2 * 64 + col] = O[nb][2] * a2;
        osc[rl2 * 64 + col + 1] = O[nb][3] * a2;
      }
    }
    __syncthreads();
    if (team == 0) {
      const float i1 = 1.0f / L1, i2 = 1.0f / L2;
      const size_t r1o = (size_t)(b * kT + qg1) * kHD;
      const size_t r2o = (size_t)(b * kT + qg2) * kHD;
#pragma unroll
      for (int nb = 0; nb < 8; ++nb) {
        const int col = nb * 8 + tg * 2;
        *(float2*)(out + r1o + col) = make_float2(
            (O[nb][0] * a1 + osc[rl1 * 64 + col]) * i1,
            (O[nb][1] * a1 + osc[rl1 * 64 + col + 1]) * i1);
        *(float2*)(out + r2o + col) = make_float2(
            (O[nb][2] * a2 + osc[rl2 * 64 + col]) * i2,
            (O[nb][3] * a2 + osc[rl2 * 64 + col + 1]) * i2);
      }
    }
  }
}

// ---------------------------------------------------------------------------
extern "C" void kernel_launch(void* const* d_in, const int* in_sizes, int n_in,
                              void* d_out, int out_size) {
  const float* x  = (const float*)d_in[0];
  const float* Wq = (const float*)d_in[1];
  const float* Wk = (const float*)d_in[2];
  const float* Wv = (const float*)d_in[3];
  const int*   pm = (const int*)d_in[4];
  float* out = (float*)d_out;

  cudaFuncSetAttribute(proj_kernel, cudaFuncAttributeMaxDynamicSharedMemorySize,
                       kProjSmem);
  cudaFuncSetAttribute(attn_kernel, cudaFuncAttributeMaxDynamicSharedMemorySize,
                       kAttnSmem);

  wsplit_kernel<<<192, 256>>>(Wq, Wk, Wv);
  proj_kernel<<<kM / 128, 256, kProjSmem>>>(x);
  attn_kernel<<<dim3(32, kB), 256, kAttnSmem>>>(pm, out);
}